// round 5
// baseline (speedup 1.0000x reference)
#include <cuda_runtime.h>
#include <cstdint>

// GlobalShift2dV2Portion: (16, 512, 64, 64) fp32.
// Channels [0,256): identity. Channels [256,512): per channel-group g=(c-256)>>4,
// the 16 spatial 16x16 blocks (t = a*4+e) are cyclically rotated:
//   out block t' = (t - g) mod 16 receives input block t.
//
// R5: scatter formulation (linear demand reads, buffered permuted writes),
// 8 independent float4 per thread for deeper MLP and fewer wave transitions.

static __device__ __forceinline__ unsigned dst_of(unsigned i)
{
    unsigned w4 = i & 15u;           // float4 within 64-float row
    unsigned h  = (i >> 4) & 63u;
    unsigned c  = (i >> 10) & 511u;

    if (c < 256u) return i;

    unsigned g   = (c - 256u) >> 4;  // channel group (rotation amount)
    unsigned a   = h >> 4;           // input spatial block row
    unsigned hh  = h & 15u;
    unsigned e   = w4 >> 2;          // input spatial block col
    unsigned ww4 = w4 & 3u;
    unsigned t   = a * 4u + e;       // input block index
    unsigned tp  = (t + 16u - g) & 15u;   // output block index (inverse rot)
    unsigned base = i & ~1023u;      // (b,c) plane base in float4
    return base + (((tp >> 2) * 16u + hh) << 4) + (tp & 3u) * 4u + ww4;
}

__global__ void __launch_bounds__(256) shift_scatter_kernel(
    const float4* __restrict__ in, float4* __restrict__ out)
{
    const unsigned STRIDE = 1u << 20;               // n4 / 8
    const unsigned i0 = blockIdx.x * 256u + threadIdx.x;  // [0, 2^20)

    float4 v[8];
    // Front-batched linear reads (MLP=8), streaming policy.
    #pragma unroll
    for (int k = 0; k < 8; k++)
        v[k] = __ldcs(in + i0 + (unsigned)k * STRIDE);

    // Permuted fire-and-forget stores.
    #pragma unroll
    for (int k = 0; k < 8; k++)
        __stcs(out + dst_of(i0 + (unsigned)k * STRIDE), v[k]);
}

extern "C" void kernel_launch(void* const* d_in, const int* in_sizes, int n_in,
                              void* d_out, int out_size)
{
    const float4* in  = (const float4*)d_in[0];
    float4*       out = (float4*)d_out;
    // n4 = 2^23 float4 total; 8 per thread -> 2^20 threads -> 4096 blocks of 256
    shift_scatter_kernel<<<4096, 256>>>(in, out);
}